// round 15
// baseline (speedup 1.0000x reference)
#include <cuda_runtime.h>
#include <cstdint>

// ---------------------------------------------------------------------------
// Problem constants
// ---------------------------------------------------------------------------
#define BATCH   2
#define SEQ     2048
#define DMODEL  1024
#define DINNER  2048
#define DSTATE  16
#define DTRANK  64
#define NTOK    (BATCH * SEQ)          // 4096 tokens
#define XPROJ_N (DTRANK + 2 * DSTATE)  // 96
#define NSPLIT  8                      // deterministic split-K for x_proj GEMM

// ---------------------------------------------------------------------------
// Static device scratch (no dynamic allocation allowed)
// ---------------------------------------------------------------------------
__device__ float g_xz   [(size_t)NTOK * 2 * DINNER];      // 4096 x 4096  (u | z)
__device__ float g_us   [(size_t)NTOK * DINNER];          // conv+SiLU output
__device__ float g_xdbl [(size_t)NTOK * XPROJ_N];         // dtr | B | C
__device__ float g_xdblp[(size_t)NSPLIT * NTOK * XPROJ_N];// split-K partials
__device__ float g_dt   [(size_t)NTOK * DINNER];          // softplus(dt)
__device__ float g_yg   [(size_t)NTOK * DINNER];          // gated scan output

// ---------------------------------------------------------------------------
// Helpers
// ---------------------------------------------------------------------------
__device__ __forceinline__ float softplus_f(float x) {
    // max(x,0) + log1p(exp(-|x|))  — matches jax.nn.softplus
    float t = __expf(-fabsf(x));
    return fmaxf(x, 0.f) + log1pf(t);
}

__device__ __forceinline__ float silu_f(float x) {
    return x / (1.f + __expf(-x));
}

// ---------------------------------------------------------------------------
// Tiled fp32 GEMM:  C[M,N] = A[M,K] @ B[N,K]^T   (A, B row-major)
//   - 128x128 block tile, BK=8, 256 threads, 8x8 register micro-tile
//   - lda/ldb/ldc row strides (elements)
//   - split-K via blockIdx.z: k-range = [kBeg0 + z*kLen, +kLen),
//     each split writes C + z*cSplitStride (deterministic, reduced later)
//   - EPI==1: fused softplus(acc + bias[n]) epilogue (dt projection)
//   - M must be a multiple of 128 and kLen of 8 (true for all call sites);
//     N is guarded.
// ---------------------------------------------------------------------------
template <int EPI>
__global__ __launch_bounds__(256, 2)
void sgemm_tn(const float* __restrict__ A, int lda,
              const float* __restrict__ B, int ldb,
              float* __restrict__ C, int ldc,
              int M, int N, int kBeg0, int kLen,
              size_t cSplitStride, const float* __restrict__ bias)
{
    __shared__ float As[8][128];
    __shared__ float Bs[8][128];

    const int tid = threadIdx.x;
    const int bm  = blockIdx.y * 128;
    const int bn  = blockIdx.x * 128;
    const int kBeg = kBeg0 + blockIdx.z * kLen;
    C += (size_t)blockIdx.z * cSplitStride;

    // global -> smem loader mapping: 256 threads x float4 = 1024 floats/tile
    const int lr = tid >> 1;           // 0..127 : row within tile
    const int lc = (tid & 1) << 2;     // 0 or 4 : k offset within BK

    const float* Ap = A + (size_t)(bm + lr) * lda + kBeg + lc;
    const float* Bp = B + (size_t)(bn + lr) * ldb + kBeg + lc;
    const bool bval = (bn + lr) < N;

    const int tx = tid & 15;           // n micro-tile
    const int ty = tid >> 4;           // m micro-tile

    float acc[8][8];
#pragma unroll
    for (int i = 0; i < 8; i++)
#pragma unroll
        for (int j = 0; j < 8; j++) acc[i][j] = 0.f;

    for (int kt = 0; kt < kLen; kt += 8) {
        float4 av = *reinterpret_cast<const float4*>(Ap);
        float4 bv = bval ? *reinterpret_cast<const float4*>(Bp)
                         : make_float4(0.f, 0.f, 0.f, 0.f);
        __syncthreads();
        As[lc + 0][lr] = av.x; As[lc + 1][lr] = av.y;
        As[lc + 2][lr] = av.z; As[lc + 3][lr] = av.w;
        Bs[lc + 0][lr] = bv.x; Bs[lc + 1][lr] = bv.y;
        Bs[lc + 2][lr] = bv.z; Bs[lc + 3][lr] = bv.w;
        __syncthreads();

#pragma unroll
        for (int k = 0; k < 8; k++) {
            float a[8], b[8];
            *reinterpret_cast<float4*>(&a[0]) = *reinterpret_cast<const float4*>(&As[k][ty * 8]);
            *reinterpret_cast<float4*>(&a[4]) = *reinterpret_cast<const float4*>(&As[k][ty * 8 + 4]);
            *reinterpret_cast<float4*>(&b[0]) = *reinterpret_cast<const float4*>(&Bs[k][tx * 8]);
            *reinterpret_cast<float4*>(&b[4]) = *reinterpret_cast<const float4*>(&Bs[k][tx * 8 + 4]);
#pragma unroll
            for (int i = 0; i < 8; i++)
#pragma unroll
                for (int j = 0; j < 8; j++)
                    acc[i][j] = fmaf(a[i], b[j], acc[i][j]);
        }
        Ap += 8;
        Bp += 8;
    }

#pragma unroll
    for (int i = 0; i < 8; i++) {
        const int m = bm + ty * 8 + i;
        float* Cr = C + (size_t)m * ldc;
#pragma unroll
        for (int j = 0; j < 8; j++) {
            const int n = bn + tx * 8 + j;
            if (n < N) {
                float v = acc[i][j];
                if (EPI == 1) v = softplus_f(v + bias[n]);
                Cr[n] = v;
            }
        }
    }
}

// ---------------------------------------------------------------------------
// Deterministic split-K reduction for x_proj partials
// ---------------------------------------------------------------------------
__global__ void reduce_splits_kernel(const float* __restrict__ p,
                                     float* __restrict__ o, int n)
{
    int i = blockIdx.x * 256 + threadIdx.x;
    if (i < n) {
        float s = 0.f;
#pragma unroll
        for (int z = 0; z < NSPLIT; z++) s += p[(size_t)z * n + i];
        o[i] = s;
    }
}

// ---------------------------------------------------------------------------
// Causal depthwise conv1d (D_CONV=4) + bias + SiLU on the u half of xz.
// One thread per (b, t, d); loads coalesced along d.
// ---------------------------------------------------------------------------
__global__ __launch_bounds__(256)
void conv_silu_kernel(const float* __restrict__ xz,
                      const float* __restrict__ cw,
                      const float* __restrict__ cb,
                      float* __restrict__ us)
{
    size_t idx = (size_t)blockIdx.x * 256 + threadIdx.x; // 0 .. NTOK*DINNER-1
    int d = (int)(idx & (DINNER - 1));
    int t = (int)((idx >> 11) & (SEQ - 1));
    // b = idx >> 22 implicitly encoded in token index below
    const float* base = xz + (idx >> 11) * (size_t)(2 * DINNER) + d;

    float4 w = *reinterpret_cast<const float4*>(cw + 4 * d); // conv_w[d][0..3]
    float acc = cb[d];
    const ptrdiff_t S = 2 * DINNER; // token stride inside xz

    if (t >= 3) {
        acc += w.x * base[-3 * S] + w.y * base[-2 * S] + w.z * base[-S] + w.w * base[0];
    } else {
        acc += w.w * base[0];
        if (t >= 1) acc += w.z * base[-S];
        if (t >= 2) acc += w.y * base[-2 * S];
    }
    us[idx] = silu_f(acc);
}

// ---------------------------------------------------------------------------
// Selective scan + skip (D*u) + gating y*silu(z), fused.
// Grid: (DINNER/16, BATCH); block 256 threads = 16 channels x 16 states.
// h kept in a register; 16-lane shfl_xor reduction for y; 64-step smem chunks.
// ---------------------------------------------------------------------------
__global__ __launch_bounds__(256)
void scan_kernel(const float* __restrict__ dt,
                 const float* __restrict__ us,
                 const float* __restrict__ xdbl,
                 const float* __restrict__ A_log,
                 const float* __restrict__ Dp,
                 const float* __restrict__ xz,
                 float* __restrict__ yg)
{
    const int CH = 64;
    __shared__ float s_dt[CH][16], s_u[CH][16], s_z[CH][16];
    __shared__ float s_B[CH][16],  s_C[CH][16];

    const int tid  = threadIdx.x;
    const int s    = tid & 15;          // state index
    const int dd   = (tid >> 4) & 15;   // channel within block
    const int dcol = blockIdx.x * 16;
    const int d    = dcol + dd;
    const int b    = blockIdx.y;

    const float A  = -__expf(A_log[d * DSTATE + s]);  // = -exp(A_log)
    const float Dv = Dp[d];
    float h = 0.f;

    const size_t tokBase = (size_t)b * SEQ;

    for (int t0 = 0; t0 < SEQ; t0 += CH) {
        __syncthreads();
        for (int i = tid; i < CH * 16; i += 256) {
            int tl = i >> 4, c = i & 15;
            size_t tok = tokBase + t0 + tl;
            s_dt[tl][c] = dt[tok * DINNER + dcol + c];
            s_u [tl][c] = us[tok * DINNER + dcol + c];
            s_z [tl][c] = xz[tok * (size_t)(2 * DINNER) + DINNER + dcol + c];
            s_B [tl][c] = xdbl[tok * XPROJ_N + DTRANK + c];
            s_C [tl][c] = xdbl[tok * XPROJ_N + DTRANK + DSTATE + c];
        }
        __syncthreads();

#pragma unroll 4
        for (int tl = 0; tl < CH; tl++) {
            float dtv = s_dt[tl][dd];
            float uv  = s_u[tl][dd];
            float dA  = __expf(dtv * A);
            h = fmaf(dA, h, dtv * uv * s_B[tl][s]);
            float yp = h * s_C[tl][s];
            // reduce over the 16 states (stays within half-warp)
            yp += __shfl_xor_sync(0xffffffffu, yp, 8);
            yp += __shfl_xor_sync(0xffffffffu, yp, 4);
            yp += __shfl_xor_sync(0xffffffffu, yp, 2);
            yp += __shfl_xor_sync(0xffffffffu, yp, 1);
            if (s == 0) {
                float y  = fmaf(uv, Dv, yp);         // + D * u skip
                float zv = s_z[tl][dd];
                yg[(tokBase + t0 + tl) * DINNER + d] = y * silu_f(zv);
            }
        }
    }
}

// ---------------------------------------------------------------------------
// Launch
// ---------------------------------------------------------------------------
extern "C" void kernel_launch(void* const* d_in, const int* in_sizes, int n_in,
                              void* d_out, int out_size)
{
    (void)in_sizes; (void)n_in; (void)out_size;

    const float* x      = (const float*)d_in[0];
    const float* W_in   = (const float*)d_in[1];
    const float* conv_w = (const float*)d_in[2];
    const float* conv_b = (const float*)d_in[3];
    const float* W_xp   = (const float*)d_in[4];
    const float* W_dt   = (const float*)d_in[5];
    const float* b_dt   = (const float*)d_in[6];
    const float* A_log  = (const float*)d_in[7];
    const float* Dp     = (const float*)d_in[8];
    const float* W_out  = (const float*)d_in[9];
    float* out = (float*)d_out;

    float *xz, *us, *xdbl, *xdblp, *dt, *yg;
    cudaGetSymbolAddress((void**)&xz,    g_xz);
    cudaGetSymbolAddress((void**)&us,    g_us);
    cudaGetSymbolAddress((void**)&xdbl,  g_xdbl);
    cudaGetSymbolAddress((void**)&xdblp, g_xdblp);
    cudaGetSymbolAddress((void**)&dt,    g_dt);
    cudaGetSymbolAddress((void**)&yg,    g_yg);

    // 1) in_proj: xz = x @ W_in^T          (4096 x 4096, K=1024)
    sgemm_tn<0><<<dim3(2 * DINNER / 128, NTOK / 128, 1), 256>>>(
        x, DMODEL, W_in, DMODEL, xz, 2 * DINNER,
        NTOK, 2 * DINNER, 0, DMODEL, 0, nullptr);

    // 2) causal depthwise conv + SiLU on u half
    conv_silu_kernel<<<(NTOK * DINNER) / 256, 256>>>(xz, conv_w, conv_b, us);

    // 3) x_proj: x_dbl = u_silu @ W_xproj^T (4096 x 96, K=2048), split-K=8
    sgemm_tn<0><<<dim3(1, NTOK / 128, NSPLIT), 256>>>(
        us, DINNER, W_xp, DINNER, xdblp, XPROJ_N,
        NTOK, XPROJ_N, 0, DINNER / NSPLIT, (size_t)NTOK * XPROJ_N, nullptr);
    reduce_splits_kernel<<<(NTOK * XPROJ_N + 255) / 256, 256>>>(
        xdblp, xdbl, NTOK * XPROJ_N);

    // 4) dt = softplus(dtr @ W_dt^T + b_dt) (4096 x 2048, K=64), fused epilogue
    sgemm_tn<1><<<dim3(DINNER / 128, NTOK / 128, 1), 256>>>(
        xdbl, XPROJ_N, W_dt, DTRANK, dt, DINNER,
        NTOK, DINNER, 0, DTRANK, 0, b_dt);

    // 5) selective scan + D*u skip + y*silu(z) gating, fused
    scan_kernel<<<dim3(DINNER / 16, BATCH), 256>>>(
        dt, us, xdbl, A_log, Dp, xz, yg);

    // 6) out_proj: out = y_gated @ W_out^T  (4096 x 1024, K=2048)
    sgemm_tn<0><<<dim3(DMODEL / 128, NTOK / 128, 1), 256>>>(
        yg, DINNER, W_out, DINNER, out, DMODEL,
        NTOK, DMODEL, 0, DINNER, 0, nullptr);
}

// round 16
// speedup vs baseline: 1.0900x; 1.0900x over previous
#include <cuda_runtime.h>
#include <cstdint>

// ---------------------------------------------------------------------------
// Problem constants
// ---------------------------------------------------------------------------
#define BATCH   2
#define SEQ     2048
#define DMODEL  1024
#define DINNER  2048
#define DSTATE  16
#define DTRANK  64
#define NTOK    (BATCH * SEQ)          // 4096 tokens
#define XPROJ_N (DTRANK + 2 * DSTATE)  // 96
#define NSPLIT  8                      // deterministic split-K for x_proj GEMM

// ---------------------------------------------------------------------------
// Static device scratch (no dynamic allocation allowed)
// ---------------------------------------------------------------------------
__device__ float g_xz   [(size_t)NTOK * 2 * DINNER];      // 4096 x 4096  (u | z)
__device__ float g_us   [(size_t)NTOK * DINNER];          // conv+SiLU output
__device__ float g_xdbl [(size_t)NTOK * XPROJ_N];         // dtr | B | C
__device__ float g_xdblp[(size_t)NSPLIT * NTOK * XPROJ_N];// split-K partials
__device__ float g_dt   [(size_t)NTOK * DINNER];          // softplus(dt)
__device__ float g_yg   [(size_t)NTOK * DINNER];          // gated scan output

// ---------------------------------------------------------------------------
// Helpers
// ---------------------------------------------------------------------------
__device__ __forceinline__ float softplus_f(float x) {
    float t = __expf(-fabsf(x));
    return fmaxf(x, 0.f) + log1pf(t);
}

__device__ __forceinline__ float silu_f(float x) {
    return x / (1.f + __expf(-x));
}

// Packed fp32x2 FMA (Blackwell FFMA2): d = a*b + c elementwise on 2 floats.
// ptxas never emits this from C++; PTX fma.rn.f32x2 is the only path.
#define FFMA2(acc, aa, bb) \
    asm("fma.rn.f32x2 %0, %1, %2, %0;" : "+l"(acc) : "l"(aa), "l"(bb))

// ---------------------------------------------------------------------------
// Tiled fp32 GEMM:  C[M,N] = A[M,K] @ B[N,K]^T   (A, B row-major)
//   - 128x128 block tile, BK=8, 256 threads, 8x8 register micro-tile
//   - inner product uses packed fma.rn.f32x2 (2x fp32 rate on sm_103a)
//   - split-K via blockIdx.z (deterministic partials, reduced later)
//   - EPI==1: fused softplus(acc + bias[n]) epilogue (dt projection)
// ---------------------------------------------------------------------------
template <int EPI>
__global__ __launch_bounds__(256, 2)
void sgemm_tn(const float* __restrict__ A, int lda,
              const float* __restrict__ B, int ldb,
              float* __restrict__ C, int ldc,
              int M, int N, int kBeg0, int kLen,
              size_t cSplitStride, const float* __restrict__ bias)
{
    __shared__ float As[8][128];
    __shared__ float Bs[8][128];

    const int tid = threadIdx.x;
    const int bm  = blockIdx.y * 128;
    const int bn  = blockIdx.x * 128;
    const int kBeg = kBeg0 + blockIdx.z * kLen;
    C += (size_t)blockIdx.z * cSplitStride;

    // global -> smem loader mapping: 256 threads x float4 = 1024 floats/tile
    const int lr = tid >> 1;           // 0..127 : row within tile
    const int lc = (tid & 1) << 2;     // 0 or 4 : k offset within BK

    const float* Ap = A + (size_t)(bm + lr) * lda + kBeg + lc;
    const float* Bp = B + (size_t)(bn + lr) * ldb + kBeg + lc;
    const bool bval = (bn + lr) < N;

    const int tx = tid & 15;           // n micro-tile
    const int ty = tid >> 4;           // m micro-tile

    // acc pairs packed along n: acc2[i][j2] holds C(m_i, n_{2j2}), C(m_i, n_{2j2+1})
    unsigned long long acc2[8][4];
#pragma unroll
    for (int i = 0; i < 8; i++)
#pragma unroll
        for (int j = 0; j < 4; j++) acc2[i][j] = 0ull;

    for (int kt = 0; kt < kLen; kt += 8) {
        float4 av = *reinterpret_cast<const float4*>(Ap);
        float4 bv = bval ? *reinterpret_cast<const float4*>(Bp)
                         : make_float4(0.f, 0.f, 0.f, 0.f);
        __syncthreads();
        As[lc + 0][lr] = av.x; As[lc + 1][lr] = av.y;
        As[lc + 2][lr] = av.z; As[lc + 3][lr] = av.w;
        Bs[lc + 0][lr] = bv.x; Bs[lc + 1][lr] = bv.y;
        Bs[lc + 2][lr] = bv.z; Bs[lc + 3][lr] = bv.w;
        __syncthreads();

#pragma unroll
        for (int k = 0; k < 8; k++) {
            float4 a0 = *reinterpret_cast<const float4*>(&As[k][ty * 8]);
            float4 a1 = *reinterpret_cast<const float4*>(&As[k][ty * 8 + 4]);
            ulonglong2 bq0 = *reinterpret_cast<const ulonglong2*>(&Bs[k][tx * 8]);
            ulonglong2 bq1 = *reinterpret_cast<const ulonglong2*>(&Bs[k][tx * 8 + 4]);
            float avr[8] = {a0.x, a0.y, a0.z, a0.w, a1.x, a1.y, a1.z, a1.w};
#pragma unroll
            for (int i = 0; i < 8; i++) {
                unsigned long long aa;
                unsigned int au = __float_as_uint(avr[i]);
                asm("mov.b64 %0, {%1, %1};" : "=l"(aa) : "r"(au));
                FFMA2(acc2[i][0], aa, bq0.x);
                FFMA2(acc2[i][1], aa, bq0.y);
                FFMA2(acc2[i][2], aa, bq1.x);
                FFMA2(acc2[i][3], aa, bq1.y);
            }
        }
        Ap += 8;
        Bp += 8;
    }

#pragma unroll
    for (int i = 0; i < 8; i++) {
        const int m = bm + ty * 8 + i;
        float* Cr = C + (size_t)m * ldc;
#pragma unroll
        for (int j2 = 0; j2 < 4; j2++) {
            unsigned int lo, hi;
            asm("mov.b64 {%0, %1}, %2;" : "=r"(lo), "=r"(hi) : "l"(acc2[i][j2]));
            const int n = bn + tx * 8 + j2 * 2;
            if (n < N) {
                float v = __uint_as_float(lo);
                if (EPI == 1) v = softplus_f(v + bias[n]);
                Cr[n] = v;
            }
            if (n + 1 < N) {
                float v = __uint_as_float(hi);
                if (EPI == 1) v = softplus_f(v + bias[n + 1]);
                Cr[n + 1] = v;
            }
        }
    }
}

// ---------------------------------------------------------------------------
// Deterministic split-K reduction for x_proj partials
// ---------------------------------------------------------------------------
__global__ void reduce_splits_kernel(const float* __restrict__ p,
                                     float* __restrict__ o, int n)
{
    int i = blockIdx.x * 256 + threadIdx.x;
    if (i < n) {
        float s = 0.f;
#pragma unroll
        for (int z = 0; z < NSPLIT; z++) s += p[(size_t)z * n + i];
        o[i] = s;
    }
}

// ---------------------------------------------------------------------------
// Causal depthwise conv1d (D_CONV=4) + bias + SiLU on the u half of xz.
// ---------------------------------------------------------------------------
__global__ __launch_bounds__(256)
void conv_silu_kernel(const float* __restrict__ xz,
                      const float* __restrict__ cw,
                      const float* __restrict__ cb,
                      float* __restrict__ us)
{
    size_t idx = (size_t)blockIdx.x * 256 + threadIdx.x; // 0 .. NTOK*DINNER-1
    int d = (int)(idx & (DINNER - 1));
    int t = (int)((idx >> 11) & (SEQ - 1));
    const float* base = xz + (idx >> 11) * (size_t)(2 * DINNER) + d;

    float4 w = *reinterpret_cast<const float4*>(cw + 4 * d); // conv_w[d][0..3]
    float acc = cb[d];
    const ptrdiff_t S = 2 * DINNER; // token stride inside xz

    if (t >= 3) {
        acc += w.x * base[-3 * S] + w.y * base[-2 * S] + w.z * base[-S] + w.w * base[0];
    } else {
        acc += w.w * base[0];
        if (t >= 1) acc += w.z * base[-S];
        if (t >= 2) acc += w.y * base[-2 * S];
    }
    us[idx] = silu_f(acc);
}

// ---------------------------------------------------------------------------
// Selective scan + skip (D*u) + gating y*silu(z), fused.
// Grid: (DINNER/16, BATCH); block 256 threads = 16 channels x 16 states.
// ---------------------------------------------------------------------------
__global__ __launch_bounds__(256)
void scan_kernel(const float* __restrict__ dt,
                 const float* __restrict__ us,
                 const float* __restrict__ xdbl,
                 const float* __restrict__ A_log,
                 const float* __restrict__ Dp,
                 const float* __restrict__ xz,
                 float* __restrict__ yg)
{
    const int CH = 64;
    __shared__ float s_dt[CH][16], s_u[CH][16], s_z[CH][16];
    __shared__ float s_B[CH][16],  s_C[CH][16];

    const int tid  = threadIdx.x;
    const int s    = tid & 15;          // state index
    const int dd   = (tid >> 4) & 15;   // channel within block
    const int dcol = blockIdx.x * 16;
    const int d    = dcol + dd;
    const int b    = blockIdx.y;

    const float A  = -__expf(A_log[d * DSTATE + s]);  // = -exp(A_log)
    const float Dv = Dp[d];
    float h = 0.f;

    const size_t tokBase = (size_t)b * SEQ;

    for (int t0 = 0; t0 < SEQ; t0 += CH) {
        __syncthreads();
        for (int i = tid; i < CH * 16; i += 256) {
            int tl = i >> 4, c = i & 15;
            size_t tok = tokBase + t0 + tl;
            s_dt[tl][c] = dt[tok * DINNER + dcol + c];
            s_u [tl][c] = us[tok * DINNER + dcol + c];
            s_z [tl][c] = xz[tok * (size_t)(2 * DINNER) + DINNER + dcol + c];
            s_B [tl][c] = xdbl[tok * XPROJ_N + DTRANK + c];
            s_C [tl][c] = xdbl[tok * XPROJ_N + DTRANK + DSTATE + c];
        }
        __syncthreads();

#pragma unroll 4
        for (int tl = 0; tl < CH; tl++) {
            float dtv = s_dt[tl][dd];
            float uv  = s_u[tl][dd];
            float dA  = __expf(dtv * A);
            h = fmaf(dA, h, dtv * uv * s_B[tl][s]);
            float yp = h * s_C[tl][s];
            yp += __shfl_xor_sync(0xffffffffu, yp, 8);
            yp += __shfl_xor_sync(0xffffffffu, yp, 4);
            yp += __shfl_xor_sync(0xffffffffu, yp, 2);
            yp += __shfl_xor_sync(0xffffffffu, yp, 1);
            if (s == 0) {
                float y  = fmaf(uv, Dv, yp);         // + D * u skip
                float zv = s_z[tl][dd];
                yg[(tokBase + t0 + tl) * DINNER + d] = y * silu_f(zv);
            }
        }
    }
}

// ---------------------------------------------------------------------------
// Launch
// ---------------------------------------------------------------------------
extern "C" void kernel_launch(void* const* d_in, const int* in_sizes, int n_in,
                              void* d_out, int out_size)
{
    (void)in_sizes; (void)n_in; (void)out_size;

    const float* x      = (const float*)d_in[0];
    const float* W_in   = (const float*)d_in[1];
    const float* conv_w = (const float*)d_in[2];
    const float* conv_b = (const float*)d_in[3];
    const float* W_xp   = (const float*)d_in[4];
    const float* W_dt   = (const float*)d_in[5];
    const float* b_dt   = (const float*)d_in[6];
    const float* A_log  = (const float*)d_in[7];
    const float* Dp     = (const float*)d_in[8];
    const float* W_out  = (const float*)d_in[9];
    float* out = (float*)d_out;

    float *xz, *us, *xdbl, *xdblp, *dt, *yg;
    cudaGetSymbolAddress((void**)&xz,    g_xz);
    cudaGetSymbolAddress((void**)&us,    g_us);
    cudaGetSymbolAddress((void**)&xdbl,  g_xdbl);
    cudaGetSymbolAddress((void**)&xdblp, g_xdblp);
    cudaGetSymbolAddress((void**)&dt,    g_dt);
    cudaGetSymbolAddress((void**)&yg,    g_yg);

    // 1) in_proj: xz = x @ W_in^T          (4096 x 4096, K=1024)
    sgemm_tn<0><<<dim3(2 * DINNER / 128, NTOK / 128, 1), 256>>>(
        x, DMODEL, W_in, DMODEL, xz, 2 * DINNER,
        NTOK, 2 * DINNER, 0, DMODEL, 0, nullptr);

    // 2) causal depthwise conv + SiLU on u half
    conv_silu_kernel<<<(NTOK * DINNER) / 256, 256>>>(xz, conv_w, conv_b, us);

    // 3) x_proj: x_dbl = u_silu @ W_xproj^T (4096 x 96, K=2048), split-K=8
    sgemm_tn<0><<<dim3(1, NTOK / 128, NSPLIT), 256>>>(
        us, DINNER, W_xp, DINNER, xdblp, XPROJ_N,
        NTOK, XPROJ_N, 0, DINNER / NSPLIT, (size_t)NTOK * XPROJ_N, nullptr);
    reduce_splits_kernel<<<(NTOK * XPROJ_N + 255) / 256, 256>>>(
        xdblp, xdbl, NTOK * XPROJ_N);

    // 4) dt = softplus(dtr @ W_dt^T + b_dt) (4096 x 2048, K=64), fused epilogue
    sgemm_tn<1><<<dim3(DINNER / 128, NTOK / 128, 1), 256>>>(
        xdbl, XPROJ_N, W_dt, DTRANK, dt, DINNER,
        NTOK, DINNER, 0, DTRANK, 0, b_dt);

    // 5) selective scan + D*u skip + y*silu(z) gating, fused
    scan_kernel<<<dim3(DINNER / 16, BATCH), 256>>>(
        dt, us, xdbl, A_log, Dp, xz, yg);

    // 6) out_proj: out = y_gated @ W_out^T  (4096 x 1024, K=2048)
    sgemm_tn<0><<<dim3(DMODEL / 128, NTOK / 128, 1), 256>>>(
        yg, DINNER, W_out, DINNER, out, DMODEL,
        NTOK, DMODEL, 0, DINNER, 0, nullptr);
}